// round 16
// baseline (speedup 1.0000x reference)
#include <cuda_runtime.h>
#include <cstdint>

// x [2048, 17, 64, 32] fp32 ->
//  heatmap      [2048,3,16,8]  softmax over 128 of group-summed resized maps
//  max_response [2048,3]       group mean of per-channel maxes of resized maps
//  max_index    [2048,17,2]    (idx%8, idx/8) of per-channel argmax
// resize = jax.image.resize 'linear' (antialias) 1/4: separable 8-tap triangle
// {1,3,5,7,7,5,3,1}/32, border outputs renormalized x(32/28).
//
// R16: same per-warp streaming pipeline as R14/R15 (the 81% DRAM plateau),
// but with 32-row (4KB) chunks: NSLOTS=3, wait_group 1, 2 chunks (8KB --
// identical in-flight bytes) pending, refill-before-process. Sync/wait/commit
// events per byte are HALVED. One warp per CTA (finest granularity, tied-best).

#define VB_STRIDE 37          // 32 + 2 pad each side + 1
#define CHUNK_FLOATS 1024     // 32 rows x 32 cols (4 KB)
#define NSLOTS 3

__device__ __forceinline__ void cp_async16(uint32_t dst, const float* src) {
    asm volatile("cp.async.cg.shared.global [%0], [%1], 16;\n"
                 :: "r"(dst), "l"(src));
}
#define CP_COMMIT() asm volatile("cp.async.commit_group;\n" ::: "memory")
#define CP_WAIT1()  asm volatile("cp.async.wait_group 1;\n" ::: "memory")

__global__ __launch_bounds__(32)
void heatmap_kernel(const float* __restrict__ x, float* __restrict__ out)
{
    __shared__ float ring[NSLOTS][CHUNK_FLOATS];   // 12 KB
    __shared__ float hbuf[16 * VB_STRIDE];         // 2.3 KB

    const int lane = threadIdx.x;
    const int t    = blockIdx.x;                   // 0..6143
    const int g    = 2 - (t >> 11);                // longest first
    const int n    = t & 2047;

    const int ch_beg = (g == 0) ? 0 : (g == 1 ? 5 : 11);
    const int nch    = (g == 0) ? 5 : 6;
    const int Q      = nch * 2;                    // 4KB chunks in task

    const float W0 = 1.f / 32.f, W1 = 3.f / 32.f, W2 = 5.f / 32.f, W3 = 7.f / 32.f;
    const float Wt[8] = { W0, W1, W2, W3, W3, W2, W1, W0 };

    // zero hbuf pad columns once (cols 0,1 and 34,35 of 16 rows)
    {
        int vr0 = lane >> 1;
        int o   = (lane & 1) ? 34 : 0;
        hbuf[vr0 * VB_STRIDE + o]     = 0.f;
        hbuf[vr0 * VB_STRIDE + o + 1] = 0.f;
    }

    // cp.async lane geometry: 8 rounds x (4 rows, 8 lanes x 16B per row)
    const int prow = lane >> 3;          // 0..3
    const int pcol = (lane & 7) * 4;     // float offset in row

    const float* __restrict__ base = x + ((size_t)n * 17 + ch_beg) * 2048;

    uint32_t ring_u32;
    {
        uint32_t a;
        asm("{ .reg .u64 t2; cvta.to.shared.u64 t2, %1; cvt.u32.u64 %0, t2; }"
            : "=r"(a) : "l"(&ring[0][0]));
        ring_u32 = a;
    }

    // prefetch 4KB chunk q into slot (one commit ALWAYS, even when q >= Q)
    #define PREFETCH(q, slotv)                                                 \
        do {                                                                   \
            if ((q) < Q) {                                                     \
                const float* s = base + (size_t)(q) * CHUNK_FLOATS;            \
                _Pragma("unroll")                                              \
                for (int rd = 0; rd < 8; ++rd) {                               \
                    int row = rd * 4 + prow;                                   \
                    cp_async16(ring_u32 +                                      \
                               (uint32_t)(((slotv) * CHUNK_FLOATS +            \
                                           row * 32 + pcol) * 4),              \
                               s + row * 32 + pcol);                           \
                }                                                              \
            }                                                                  \
            CP_COMMIT();                                                       \
        } while (0)

    // prologue: 2 chunks (8KB) pending
    PREFETCH(0, 0); PREFETCH(1, 1);

    const int vr = lane >> 1;
    const float sc_v = ((vr == 0) | (vr == 15)) ? (32.f / 28.f) : 1.f;
    const float sc_j[4] = {
        sc_v * ((4 * (lane & 1) + 0 == 0) ? (32.f / 28.f) : 1.f),
        sc_v,
        sc_v,
        sc_v * ((4 * (lane & 1) + 3 == 7) ? (32.f / 28.f) : 1.f)
    };

    float gacc[4] = { 0.f, 0.f, 0.f, 0.f };
    float summax  = 0.f;

    float vacc[16];
    #pragma unroll
    for (int i = 0; i < 16; ++i) vacc[i] = 0.f;

    int slot = 0;                        // q % 3, carried
    for (int c = ch_beg; c < ch_beg + nch; ++c) {
        const int crel = c - ch_beg;

        #pragma unroll
        for (int sub = 0; sub < 2; ++sub) {
            const int q = crel * 2 + sub;

            CP_WAIT1();                  // chunk q arrived (2 pending -> 1)
            __syncwarp();                // data visible; prior slot reads done

            // refill FIRST: slot (q+2)%3 == (q-1)%3, retired at step q-1
            int fslot = slot + 2; if (fslot >= NSLOTS) fslot -= NSLOTS;
            PREFETCH(q + 2, fslot);

            const float* sm = &ring[slot][0];
            #pragma unroll
            for (int r = 0; r < 32; ++r) {
                float v = sm[r * 32 + lane];
                const int gr  = sub * 32 + r;          // compile-time
                const int vra = (gr + 2) >> 2;
                const int ka  = gr - 4 * vra + 2;      // 0..3
                if (vra < 16) vacc[vra]     += Wt[ka]     * v;
                if (vra >= 1) vacc[vra - 1] += Wt[ka + 4] * v;
            }

            ++slot; if (slot == NSLOTS) slot = 0;
        }

        // ---- channel tail: transpose, h-pass, argmax (overlaps in-flight)
        __syncwarp();
        #pragma unroll
        for (int i = 0; i < 16; ++i)
            hbuf[i * VB_STRIDE + 2 + lane] = vacc[i];
        __syncwarp();

        float mval = -1e30f;
        int   midx = 0;
        #pragma unroll
        for (int j = 0; j < 4; ++j) {
            const int ow = 4 * (lane & 1) + j;
            const float* h = &hbuf[vr * VB_STRIDE + 4 * ow];
            float acc = h[0] * W0 + h[1] * W1 + h[2] * W2 + h[3] * W3
                      + h[4] * W3 + h[5] * W2 + h[6] * W1 + h[7] * W0;
            const float val = acc * sc_j[j];
            gacc[j] += val;
            if (val > mval) { mval = val; midx = 4 * lane + j; }
        }
        __syncwarp();   // hbuf reads complete before next channel overwrites

        #pragma unroll
        for (int off = 16; off; off >>= 1) {
            float om = __shfl_down_sync(0xffffffffu, mval, off);
            int   oi = __shfl_down_sync(0xffffffffu, midx, off);
            if (om > mval || (om == mval && oi < midx)) { mval = om; midx = oi; }
        }
        if (lane == 0) {
            summax += mval;
            const size_t o = 792576 + ((size_t)n * 17 + c) * 2;
            out[o + 0] = (float)(midx & 7);
            out[o + 1] = (float)(midx >> 3);
        }

        #pragma unroll
        for (int i = 0; i < 16; ++i) vacc[i] = 0.f;
    }
    #undef PREFETCH

    // ---- warp-local softmax over 128 group-sum values (4 per lane)
    float m = fmaxf(fmaxf(gacc[0], gacc[1]), fmaxf(gacc[2], gacc[3]));
    #pragma unroll
    for (int off = 16; off; off >>= 1)
        m = fmaxf(m, __shfl_xor_sync(0xffffffffu, m, off));

    float e0 = __expf(gacc[0] - m);
    float e1 = __expf(gacc[1] - m);
    float e2 = __expf(gacc[2] - m);
    float e3 = __expf(gacc[3] - m);
    float s  = (e0 + e1) + (e2 + e3);
    #pragma unroll
    for (int off = 16; off; off >>= 1)
        s += __shfl_xor_sync(0xffffffffu, s, off);

    const float inv = 1.f / s;
    float4 o4;
    o4.x = e0 * inv; o4.y = e1 * inv; o4.z = e2 * inv; o4.w = e3 * inv;
    *(float4*)(out + (size_t)n * 384 + (size_t)g * 128 + 4 * lane) = o4;

    if (lane == 0) {
        const float cnt = (g == 0) ? (1.f / 5.f) : (1.f / 6.f);
        out[786432 + (size_t)n * 3 + g] = summax * cnt;
    }
}

extern "C" void kernel_launch(void* const* d_in, const int* in_sizes, int n_in,
                              void* d_out, int out_size)
{
    const float* x = (const float*)d_in[0];
    float* out = (float*)d_out;
    (void)in_sizes; (void)n_in; (void)out_size;
    heatmap_kernel<<<6144, 32>>>(x, out);
}

// round 17
// speedup vs baseline: 1.0007x; 1.0007x over previous
#include <cuda_runtime.h>
#include <cstdint>

// x [2048, 17, 64, 32] fp32 ->
//  heatmap      [2048,3,16,8]  softmax over 128 of group-summed resized maps
//  max_response [2048,3]       group mean of per-channel maxes of resized maps
//  max_index    [2048,17,2]    (idx%8, idx/8) of per-channel argmax
// resize = jax.image.resize 'linear' (antialias) 1/4: separable 8-tap triangle
// {1,3,5,7,7,5,3,1}/32, border outputs renormalized x(32/28).
//
// FINAL (== R14, the measured optimum of the full structural sweep):
// warp per (n,group); cp.async.cg 5-slot ring of 16-row (2KB) chunks with
// 4 chunks (8KB) in flight, refill-before-process; vertical 8-tap in regs,
// horizontal 8-tap via tiny per-warp smem transpose; warp-local softmax /
// argmax epilogues; 2-warp CTAs (finest beneficial granularity); longest
// tasks (6-channel groups) scheduled first.

#define VB_STRIDE 37          // 32 + 2 pad each side + 1
#define WARPS_PER_CTA 2
#define CHUNK_FLOATS 512      // 16 rows x 32 cols
#define NSLOTS 5
#define PAD_FLOATS 944        // (dead; compiler-eliminated — kept for exact repro)

__device__ __forceinline__ void cp_async16(uint32_t dst, const float* src) {
    asm volatile("cp.async.cg.shared.global [%0], [%1], 16;\n"
                 :: "r"(dst), "l"(src));
}
#define CP_COMMIT() asm volatile("cp.async.commit_group;\n" ::: "memory")
#define CP_WAIT3()  asm volatile("cp.async.wait_group 3;\n" ::: "memory")

__global__ __launch_bounds__(32 * WARPS_PER_CTA, 8)
void heatmap_kernel(const float* __restrict__ x, float* __restrict__ out)
{
    __shared__ float ring[WARPS_PER_CTA][NSLOTS][CHUNK_FLOATS];  // 20 KB
    __shared__ float hbuf[WARPS_PER_CTA][16 * VB_STRIDE];        // 4.6 KB
    __shared__ float padsm[PAD_FLOATS];

    const int lane = threadIdx.x & 31;
    const int wrp  = threadIdx.x >> 5;
    const int t    = blockIdx.x * WARPS_PER_CTA + wrp;      // 0..6143
    const int g    = 2 - (t >> 11);                         // longest first
    const int n    = t & 2047;

    if (threadIdx.x == 0xFFFF) padsm[0] = 0.f;

    const int ch_beg = (g == 0) ? 0 : (g == 1 ? 5 : 11);
    const int nch    = (g == 0) ? 5 : 6;
    const int Q      = nch * 4;                              // chunks in task

    const float W0 = 1.f / 32.f, W1 = 3.f / 32.f, W2 = 5.f / 32.f, W3 = 7.f / 32.f;
    const float Wt[8] = { W0, W1, W2, W3, W3, W2, W1, W0 };

    float* wb = hbuf[wrp];

    // zero hbuf pad columns once (cols 0,1 and 34,35 of 16 rows)
    {
        int vr0 = lane >> 1;
        int o   = (lane & 1) ? 34 : 0;
        wb[vr0 * VB_STRIDE + o]     = 0.f;
        wb[vr0 * VB_STRIDE + o + 1] = 0.f;
    }

    // cp.async lane geometry: 4 rows per round, 8 lanes x 16B per row
    const int prow = lane >> 3;          // 0..3
    const int pcol = (lane & 7) * 4;     // float offset in row

    const float* __restrict__ base = x + ((size_t)n * 17 + ch_beg) * 2048;

    uint32_t ring_u32;
    {
        uint32_t a;
        asm("{ .reg .u64 t2; cvta.to.shared.u64 t2, %1; cvt.u32.u64 %0, t2; }"
            : "=r"(a) : "l"(&ring[wrp][0][0]));
        ring_u32 = a;
    }

    // prefetch chunk q into slot (one commit ALWAYS, even when q >= Q)
    #define PREFETCH(q, slotv)                                                 \
        do {                                                                   \
            if ((q) < Q) {                                                     \
                const float* s = base + (size_t)(q) * CHUNK_FLOATS;            \
                _Pragma("unroll")                                              \
                for (int rd = 0; rd < 4; ++rd) {                               \
                    int row = rd * 4 + prow;                                   \
                    cp_async16(ring_u32 +                                      \
                               (uint32_t)(((slotv) * CHUNK_FLOATS +            \
                                           row * 32 + pcol) * 4),              \
                               s + row * 32 + pcol);                           \
                }                                                              \
            }                                                                  \
            CP_COMMIT();                                                       \
        } while (0)

    // prologue: 4 chunks pending
    PREFETCH(0, 0); PREFETCH(1, 1); PREFETCH(2, 2); PREFETCH(3, 3);

    const int vr = lane >> 1;
    const float sc_v = ((vr == 0) | (vr == 15)) ? (32.f / 28.f) : 1.f;
    const float sc_j[4] = {
        sc_v * ((4 * (lane & 1) + 0 == 0) ? (32.f / 28.f) : 1.f),
        sc_v,
        sc_v,
        sc_v * ((4 * (lane & 1) + 3 == 7) ? (32.f / 28.f) : 1.f)
    };

    float gacc[4] = { 0.f, 0.f, 0.f, 0.f };
    float summax  = 0.f;

    float vacc[16];
    #pragma unroll
    for (int i = 0; i < 16; ++i) vacc[i] = 0.f;

    int slot = 0;                        // q % 5, carried
    for (int c = ch_beg; c < ch_beg + nch; ++c) {
        const int crel = c - ch_beg;

        #pragma unroll
        for (int sub = 0; sub < 4; ++sub) {
            const int q = crel * 4 + sub;

            CP_WAIT3();                  // chunk q arrived (4 pending -> 3)
            __syncwarp();                // data visible; prior slot reads done

            // refill FIRST: slot (q+4)%5 was retired at step q-1
            int fslot = slot + 4; if (fslot >= NSLOTS) fslot -= NSLOTS;
            PREFETCH(q + 4, fslot);

            const float* sm = &ring[wrp][slot][0];
            #pragma unroll
            for (int r = 0; r < 16; ++r) {
                float v = sm[r * 32 + lane];
                const int gr  = sub * 16 + r;          // compile-time
                const int vra = (gr + 2) >> 2;
                const int ka  = gr - 4 * vra + 2;      // 0..3
                if (vra < 16) vacc[vra]     += Wt[ka]     * v;
                if (vra >= 1) vacc[vra - 1] += Wt[ka + 4] * v;
            }

            ++slot; if (slot == NSLOTS) slot = 0;
        }

        // ---- channel tail: transpose, h-pass, argmax (overlaps in-flight)
        __syncwarp();
        #pragma unroll
        for (int i = 0; i < 16; ++i)
            wb[i * VB_STRIDE + 2 + lane] = vacc[i];
        __syncwarp();

        float mval = -1e30f;
        int   midx = 0;
        #pragma unroll
        for (int j = 0; j < 4; ++j) {
            const int ow = 4 * (lane & 1) + j;
            const float* h = &wb[vr * VB_STRIDE + 4 * ow];
            float acc = h[0] * W0 + h[1] * W1 + h[2] * W2 + h[3] * W3
                      + h[4] * W3 + h[5] * W2 + h[6] * W1 + h[7] * W0;
            const float val = acc * sc_j[j];
            gacc[j] += val;
            if (val > mval) { mval = val; midx = 4 * lane + j; }
        }
        __syncwarp();   // hbuf reads complete before next channel overwrites

        #pragma unroll
        for (int off = 16; off; off >>= 1) {
            float om = __shfl_down_sync(0xffffffffu, mval, off);
            int   oi = __shfl_down_sync(0xffffffffu, midx, off);
            if (om > mval || (om == mval && oi < midx)) { mval = om; midx = oi; }
        }
        if (lane == 0) {
            summax += mval;
            const size_t o = 792576 + ((size_t)n * 17 + c) * 2;
            out[o + 0] = (float)(midx & 7);
            out[o + 1] = (float)(midx >> 3);
        }

        #pragma unroll
        for (int i = 0; i < 16; ++i) vacc[i] = 0.f;
    }
    #undef PREFETCH

    // ---- warp-local softmax over 128 group-sum values (4 per lane)
    float m = fmaxf(fmaxf(gacc[0], gacc[1]), fmaxf(gacc[2], gacc[3]));
    #pragma unroll
    for (int off = 16; off; off >>= 1)
        m = fmaxf(m, __shfl_xor_sync(0xffffffffu, m, off));

    float e0 = __expf(gacc[0] - m);
    float e1 = __expf(gacc[1] - m);
    float e2 = __expf(gacc[2] - m);
    float e3 = __expf(gacc[3] - m);
    float s  = (e0 + e1) + (e2 + e3);
    #pragma unroll
    for (int off = 16; off; off >>= 1)
        s += __shfl_xor_sync(0xffffffffu, s, off);

    const float inv = 1.f / s;
    float4 o4;
    o4.x = e0 * inv; o4.y = e1 * inv; o4.z = e2 * inv; o4.w = e3 * inv;
    *(float4*)(out + (size_t)n * 384 + (size_t)g * 128 + 4 * lane) = o4;

    if (lane == 0) {
        const float cnt = (g == 0) ? (1.f / 5.f) : (1.f / 6.f);
        out[786432 + (size_t)n * 3 + g] = summax * cnt;
    }
}

extern "C" void kernel_launch(void* const* d_in, const int* in_sizes, int n_in,
                              void* d_out, int out_size)
{
    const float* x = (const float*)d_in[0];
    float* out = (float*)d_out;
    (void)in_sizes; (void)n_in; (void)out_size;
    heatmap_kernel<<<2048 * 3 / WARPS_PER_CTA, 32 * WARPS_PER_CTA>>>(x, out);
}